// round 7
// baseline (speedup 1.0000x reference)
#include <cuda_runtime.h>
#include <cuda_fp16.h>
#include <cstdint>

#define N_NODES 50000
#define E_EDGES 800000
#define ODIM 128
#define M_CNT (2 * N_NODES)            // 100000 (rel,row) buckets
#define SCAN_T 1024
#define CHUNK ((M_CNT + SCAN_T - 1) / SCAN_T)   // 98

// Projected features fp16: [n][128] half2 (rel0 = half2 cols 0..63, rel1 = 64..127)
__device__ __half2 g_x2[(size_t)N_NODES * 128];
// Row-sorted edges: (col bits, val)
__device__ float2  g_edges[(size_t)2 * E_EDGES];
__device__ int     g_counts[M_CNT];       // zero-init at load; scan re-zeroes each run
__device__ int     g_start[M_CNT + 1];
__device__ int     g_cursor[M_CNT];

// ---------------------------------------------------------------------------
// Tensor-core GEMM (tf32 x3 split) — unchanged.
// ---------------------------------------------------------------------------
#define STRIDE 132
#define GEMM_SMEM_BYTES (2 * 128 * STRIDE * 4)   // 132 KB

__device__ __forceinline__ void cvt_split(float v, uint32_t& hi, uint32_t& lo) {
    asm("cvt.rna.tf32.f32 %0, %1;" : "=r"(hi) : "f"(v));
    float r = v - __uint_as_float(hi);
    asm("cvt.rna.tf32.f32 %0, %1;" : "=r"(lo) : "f"(r));
}

__device__ __forceinline__ void mma8(float* c, const uint32_t* a,
                                     uint32_t b0, uint32_t b1) {
    asm volatile(
        "mma.sync.aligned.m16n8k8.row.col.f32.tf32.tf32.f32 "
        "{%0,%1,%2,%3}, {%4,%5,%6,%7}, {%8,%9}, {%0,%1,%2,%3};"
        : "+f"(c[0]), "+f"(c[1]), "+f"(c[2]), "+f"(c[3])
        : "r"(a[0]), "r"(a[1]), "r"(a[2]), "r"(a[3]), "r"(b0), "r"(b1));
}

__global__ void __launch_bounds__(256) gemm_tc_kernel(
    const float* __restrict__ A,
    const float* __restrict__ W1,
    const float* __restrict__ W2)
{
    extern __shared__ float smem[];
    float* As = smem;
    float* Bs = smem + 128 * STRIDE;

    const float* W = (blockIdx.y == 0) ? W1 : W2;
    const int row0 = blockIdx.x * 128;
    const int tid  = threadIdx.x;

    const float4* A4 = (const float4*)A;
    #pragma unroll
    for (int i = 0; i < 16; i++) {
        int idx = tid + i * 256;
        int m   = idx >> 5;
        int c4  = idx & 31;
        float4 v = make_float4(0.f, 0.f, 0.f, 0.f);
        if (row0 + m < N_NODES) v = A4[(size_t)(row0 + m) * 32 + c4];
        float* dst = As + m * STRIDE + c4 * 4;
        dst[0] = v.x; dst[1] = v.y; dst[2] = v.z; dst[3] = v.w;
    }
    const float4* W4 = (const float4*)W;
    #pragma unroll
    for (int i = 0; i < 16; i++) {
        int idx = tid + i * 256;
        int k   = idx >> 5;
        int n4  = idx & 31;
        float4 v = W4[idx];
        Bs[(n4 * 4 + 0) * STRIDE + k] = v.x;
        Bs[(n4 * 4 + 1) * STRIDE + k] = v.y;
        Bs[(n4 * 4 + 2) * STRIDE + k] = v.z;
        Bs[(n4 * 4 + 3) * STRIDE + k] = v.w;
    }
    __syncthreads();

    const int wid  = tid >> 5;
    const int lane = tid & 31;
    const int wm   = wid & 3;
    const int wn   = wid >> 2;
    const int g    = lane >> 2;
    const int t    = lane & 3;

    float c[2][8][4];
    #pragma unroll
    for (int mt = 0; mt < 2; mt++)
        #pragma unroll
        for (int nt = 0; nt < 8; nt++)
            #pragma unroll
            for (int j = 0; j < 4; j++) c[mt][nt][j] = 0.f;

    #pragma unroll 1
    for (int ks = 0; ks < 16; ks++) {
        const int k0 = ks * 8;
        uint32_t ah[2][4], al[2][4];
        #pragma unroll
        for (int mt = 0; mt < 2; mt++) {
            const int r0 = wm * 32 + mt * 16;
            float v0 = As[(r0 + g)     * STRIDE + k0 + t];
            float v1 = As[(r0 + g + 8) * STRIDE + k0 + t];
            float v2 = As[(r0 + g)     * STRIDE + k0 + t + 4];
            float v3 = As[(r0 + g + 8) * STRIDE + k0 + t + 4];
            cvt_split(v0, ah[mt][0], al[mt][0]);
            cvt_split(v1, ah[mt][1], al[mt][1]);
            cvt_split(v2, ah[mt][2], al[mt][2]);
            cvt_split(v3, ah[mt][3], al[mt][3]);
        }
        #pragma unroll
        for (int nt = 0; nt < 8; nt++) {
            const int n = wn * 64 + nt * 8 + g;
            float w0 = Bs[n * STRIDE + k0 + t];
            float w1 = Bs[n * STRIDE + k0 + t + 4];
            uint32_t bh0, bl0, bh1, bl1;
            cvt_split(w0, bh0, bl0);
            cvt_split(w1, bh1, bl1);
            #pragma unroll
            for (int mt = 0; mt < 2; mt++) {
                mma8(c[mt][nt], ah[mt], bh0, bh1);
                mma8(c[mt][nt], al[mt], bh0, bh1);
                mma8(c[mt][nt], ah[mt], bl0, bl1);
            }
        }
    }

    #pragma unroll
    for (int mt = 0; mt < 2; mt++) {
        #pragma unroll
        for (int nt = 0; nt < 8; nt++) {
            const int row_a = row0 + wm * 32 + mt * 16 + g;
            const int row_b = row_a + 8;
            const int h2col = blockIdx.y * 64 + wn * 32 + nt * 4 + t;
            if (row_a < N_NODES)
                g_x2[(size_t)row_a * 128 + h2col] =
                    __floats2half2_rn(c[mt][nt][0], c[mt][nt][1]);
            if (row_b < N_NODES)
                g_x2[(size_t)row_b * 128 + h2col] =
                    __floats2half2_rn(c[mt][nt][2], c[mt][nt][3]);
        }
    }
}

// ---------------------------------------------------------------------------
// Counting sort chain (3 kernels total: hist, scan, reorder)
// ---------------------------------------------------------------------------
#define E4 (E_EDGES / 4)   // 200000

__global__ void hist_kernel(const int* __restrict__ r1, const int* __restrict__ r2) {
    int t = blockIdx.x * blockDim.x + threadIdx.x;
    if (t >= 2 * E4) return;
    int rel = (t >= E4);
    const int4* rr = (const int4*)(rel ? r2 : r1);
    int4 r = __ldg(rr + (t - rel * E4));
    int base = rel * N_NODES;
    atomicAdd(&g_counts[base + r.x], 1);
    atomicAdd(&g_counts[base + r.y], 1);
    atomicAdd(&g_counts[base + r.z], 1);
    atomicAdd(&g_counts[base + r.w], 1);
}

// Single-block scan: each thread owns CHUNK consecutive counters.
// Pass 1 sums; block scan; pass 2 writes g_start/g_cursor and ZEROES g_counts
// (so the next graph replay's hist starts from zero — no memset needed).
__global__ void __launch_bounds__(SCAN_T) scan_kernel() {
    __shared__ int s[SCAN_T];
    const int t = threadIdx.x;
    const int base = t * CHUNK;

    int sum = 0;
    for (int j = 0; j < CHUNK; j++) {
        int i = base + j;
        if (i < M_CNT) sum += g_counts[i];
    }
    s[t] = sum;
    __syncthreads();
    for (int off = 1; off < SCAN_T; off <<= 1) {
        int u = (t >= off) ? s[t - off] : 0;
        __syncthreads();
        if (t >= off) s[t] += u;
        __syncthreads();
    }
    int run = s[t] - sum;   // exclusive prefix for this chunk
    for (int j = 0; j < CHUNK; j++) {
        int i = base + j;
        if (i < M_CNT) {
            int c = g_counts[i];
            g_start[i]  = run;
            g_cursor[i] = run;
            run += c;
            g_counts[i] = 0;
        }
    }
    if (t == SCAN_T - 1) g_start[M_CNT] = s[SCAN_T - 1];
}

__global__ void reorder_kernel(
    const int* __restrict__ r1, const int* __restrict__ c1, const float* __restrict__ v1,
    const int* __restrict__ r2, const int* __restrict__ c2, const float* __restrict__ v2)
{
    int t = blockIdx.x * blockDim.x + threadIdx.x;
    if (t >= 2 * E4) return;
    int rel = (t >= E4);
    int i4  = t - rel * E4;
    const int4*   rr = (const int4*)  (rel ? r2 : r1);
    const int4*   cc = (const int4*)  (rel ? c2 : c1);
    const float4* vv = (const float4*)(rel ? v2 : v1);
    int4   r = __ldg(rr + i4);
    int4   c = __ldg(cc + i4);
    float4 v = __ldg(vv + i4);
    int base = rel * N_NODES;
    int p0 = atomicAdd(&g_cursor[base + r.x], 1);
    int p1 = atomicAdd(&g_cursor[base + r.y], 1);
    int p2 = atomicAdd(&g_cursor[base + r.z], 1);
    int p3 = atomicAdd(&g_cursor[base + r.w], 1);
    g_edges[p0] = make_float2(__int_as_float(c.x), v.x);
    g_edges[p1] = make_float2(__int_as_float(c.y), v.y);
    g_edges[p2] = make_float2(__int_as_float(c.z), v.z);
    g_edges[p3] = make_float2(__int_as_float(c.w), v.w);
}

// ---------------------------------------------------------------------------
// Gather: one warp per row; 16-lane half-warps; the TWO relations' edge lists
// are walked in the SAME loop (independent load chains -> 2x MLP), each
// additionally 2x unrolled. fp16 reads, fp32 accum, fused ReLU, ST.128 out.
// ---------------------------------------------------------------------------
__device__ __forceinline__ void acc_feat(float* a, float w, float4 q) {
    float2 f0 = __half22float2(*(__half2*)&q.x);
    float2 f1 = __half22float2(*(__half2*)&q.y);
    float2 f2 = __half22float2(*(__half2*)&q.z);
    float2 f3 = __half22float2(*(__half2*)&q.w);
    a[0] += w * f0.x;  a[1] += w * f0.y;
    a[2] += w * f1.x;  a[3] += w * f1.y;
    a[4] += w * f2.x;  a[5] += w * f2.y;
    a[6] += w * f3.x;  a[7] += w * f3.y;
}

__global__ void __launch_bounds__(256) gather_kernel(float* __restrict__ out)
{
    const int w    = (blockIdx.x * blockDim.x + threadIdx.x) >> 5;
    const int lane = threadIdx.x & 31;
    if (w >= N_NODES) return;

    const int half = lane >> 4;     // 0 or 1
    const int hl   = lane & 15;     // lane in half-warp

    float a[8];
    #pragma unroll
    for (int j = 0; j < 8; j++) a[j] = 0.f;

    const float4* X4 = (const float4*)g_x2;   // [n][32] float4

    int p  = g_start[w] + half;                   // rel0 stream
    const int p_end = g_start[w + 1];
    int q  = g_start[N_NODES + w] + half;         // rel1 stream
    const int q_end = g_start[N_NODES + w + 1];

    // Main loop: 2 edges per relation per iteration = 4 independent chains.
    while (p + 2 < p_end && q + 2 < q_end) {
        float2 e0 = __ldg(&g_edges[p]);
        float2 e1 = __ldg(&g_edges[p + 2]);
        float2 e2 = __ldg(&g_edges[q]);
        float2 e3 = __ldg(&g_edges[q + 2]);
        float4 q0 = __ldg(X4 + (size_t)__float_as_int(e0.x) * 32 + hl);
        float4 q1 = __ldg(X4 + (size_t)__float_as_int(e1.x) * 32 + hl);
        float4 q2 = __ldg(X4 + (size_t)__float_as_int(e2.x) * 32 + 16 + hl);
        float4 q3 = __ldg(X4 + (size_t)__float_as_int(e3.x) * 32 + 16 + hl);
        acc_feat(a, e0.y, q0);
        acc_feat(a, e1.y, q1);
        acc_feat(a, e2.y, q2);
        acc_feat(a, e3.y, q3);
        p += 4;
        q += 4;
    }
    // Tails.
    for (; p < p_end; p += 2) {
        float2 e = __ldg(&g_edges[p]);
        float4 qv = __ldg(X4 + (size_t)__float_as_int(e.x) * 32 + hl);
        acc_feat(a, e.y, qv);
    }
    for (; q < q_end; q += 2) {
        float2 e = __ldg(&g_edges[q]);
        float4 qv = __ldg(X4 + (size_t)__float_as_int(e.x) * 32 + 16 + hl);
        acc_feat(a, e.y, qv);
    }

    // Combine the two half-warps' partials.
    #pragma unroll
    for (int j = 0; j < 8; j++)
        a[j] += __shfl_xor_sync(0xffffffff, a[j], 16);

    const int j0 = half * 4;
    float4 o;
    o.x = fmaxf(a[j0 + 0], 0.f);
    o.y = fmaxf(a[j0 + 1], 0.f);
    o.z = fmaxf(a[j0 + 2], 0.f);
    o.w = fmaxf(a[j0 + 3], 0.f);
    ((float4*)out)[(size_t)w * 32 + hl * 2 + half] = o;
}

// ---------------------------------------------------------------------------
extern "C" void kernel_launch(void* const* d_in, const int* in_sizes, int n_in,
                              void* d_out, int out_size)
{
    const float* inputs = (const float*)d_in[0];
    const int*   r1     = (const int*)  d_in[1];
    const int*   c1     = (const int*)  d_in[2];
    const float* v1     = (const float*)d_in[3];
    const int*   r2     = (const int*)  d_in[4];
    const int*   c2     = (const int*)  d_in[5];
    const float* v2     = (const float*)d_in[6];
    const float* W1     = (const float*)d_in[7];
    const float* W2     = (const float*)d_in[8];
    float*       out    = (float*)d_out;

    static cudaStream_t s_gemm = nullptr;
    static cudaEvent_t  e_fork = nullptr;
    static cudaEvent_t  e_join = nullptr;
    if (s_gemm == nullptr) {
        cudaStreamCreateWithFlags(&s_gemm, cudaStreamNonBlocking);
        cudaEventCreateWithFlags(&e_fork, cudaEventDisableTiming);
        cudaEventCreateWithFlags(&e_join, cudaEventDisableTiming);
        cudaFuncSetAttribute(gemm_tc_kernel,
                             cudaFuncAttributeMaxDynamicSharedMemorySize,
                             GEMM_SMEM_BYTES);
    }

    // Launch 0: GEMM on side stream (overlaps the sort chain).
    cudaEventRecord(e_fork, 0);
    cudaStreamWaitEvent(s_gemm, e_fork, 0);
    {
        dim3 grid((N_NODES + 127) / 128, 2);
        gemm_tc_kernel<<<grid, 256, GEMM_SMEM_BYTES, s_gemm>>>(inputs, W1, W2);
    }
    cudaEventRecord(e_join, s_gemm);

    // Launches 1-3: sort chain (counts are zeroed by the previous run's scan).
    hist_kernel<<<(2 * E4 + 255) / 256, 256>>>(r1, r2);
    scan_kernel<<<1, SCAN_T>>>();
    reorder_kernel<<<(2 * E4 + 255) / 256, 256>>>(r1, c1, v1, r2, c2, v2);

    // Launch 4: gather (profiled slot).
    cudaStreamWaitEvent(0, e_join, 0);
    {
        long warps = N_NODES;
        int blocks = (int)((warps * 32 + 255) / 256);
        gather_kernel<<<blocks, 256>>>(out);
    }
}

// round 8
// speedup vs baseline: 1.9691x; 1.9691x over previous
#include <cuda_runtime.h>
#include <cuda_fp16.h>
#include <cstdint>

#define N_NODES 50000
#define E_EDGES 800000
#define ODIM 128
#define M_CNT (2 * N_NODES)            // 100000 (rel,row) buckets
#define SCAN_B 1024
#define NBLK_SCAN ((M_CNT + SCAN_B - 1) / SCAN_B)   // 98

// Projected features fp16: [n][128] half2 (rel0 = half2 cols 0..63, rel1 = 64..127)
__device__ __half2 g_x2[(size_t)N_NODES * 128];
// Row-sorted edges: (col bits, val)
__device__ float2  g_edges[(size_t)2 * E_EDGES];
__device__ int     g_counts[M_CNT];   // zero at load; scan3 re-zeroes every run
__device__ int     g_tmp[M_CNT];
__device__ int     g_bsum[NBLK_SCAN];
__device__ int     g_start[M_CNT + 1];
__device__ int     g_cursor[M_CNT];

// ---------------------------------------------------------------------------
// Tensor-core GEMM (tf32 x3 split) — unchanged.
// ---------------------------------------------------------------------------
#define STRIDE 132
#define GEMM_SMEM_BYTES (2 * 128 * STRIDE * 4)   // 132 KB

__device__ __forceinline__ void cvt_split(float v, uint32_t& hi, uint32_t& lo) {
    asm("cvt.rna.tf32.f32 %0, %1;" : "=r"(hi) : "f"(v));
    float r = v - __uint_as_float(hi);
    asm("cvt.rna.tf32.f32 %0, %1;" : "=r"(lo) : "f"(r));
}

__device__ __forceinline__ void mma8(float* c, const uint32_t* a,
                                     uint32_t b0, uint32_t b1) {
    asm volatile(
        "mma.sync.aligned.m16n8k8.row.col.f32.tf32.tf32.f32 "
        "{%0,%1,%2,%3}, {%4,%5,%6,%7}, {%8,%9}, {%0,%1,%2,%3};"
        : "+f"(c[0]), "+f"(c[1]), "+f"(c[2]), "+f"(c[3])
        : "r"(a[0]), "r"(a[1]), "r"(a[2]), "r"(a[3]), "r"(b0), "r"(b1));
}

__global__ void __launch_bounds__(256) gemm_tc_kernel(
    const float* __restrict__ A,
    const float* __restrict__ W1,
    const float* __restrict__ W2)
{
    extern __shared__ float smem[];
    float* As = smem;
    float* Bs = smem + 128 * STRIDE;

    const float* W = (blockIdx.y == 0) ? W1 : W2;
    const int row0 = blockIdx.x * 128;
    const int tid  = threadIdx.x;

    const float4* A4 = (const float4*)A;
    #pragma unroll
    for (int i = 0; i < 16; i++) {
        int idx = tid + i * 256;
        int m   = idx >> 5;
        int c4  = idx & 31;
        float4 v = make_float4(0.f, 0.f, 0.f, 0.f);
        if (row0 + m < N_NODES) v = A4[(size_t)(row0 + m) * 32 + c4];
        float* dst = As + m * STRIDE + c4 * 4;
        dst[0] = v.x; dst[1] = v.y; dst[2] = v.z; dst[3] = v.w;
    }
    const float4* W4 = (const float4*)W;
    #pragma unroll
    for (int i = 0; i < 16; i++) {
        int idx = tid + i * 256;
        int k   = idx >> 5;
        int n4  = idx & 31;
        float4 v = W4[idx];
        Bs[(n4 * 4 + 0) * STRIDE + k] = v.x;
        Bs[(n4 * 4 + 1) * STRIDE + k] = v.y;
        Bs[(n4 * 4 + 2) * STRIDE + k] = v.z;
        Bs[(n4 * 4 + 3) * STRIDE + k] = v.w;
    }
    __syncthreads();

    const int wid  = tid >> 5;
    const int lane = tid & 31;
    const int wm   = wid & 3;
    const int wn   = wid >> 2;
    const int g    = lane >> 2;
    const int t    = lane & 3;

    float c[2][8][4];
    #pragma unroll
    for (int mt = 0; mt < 2; mt++)
        #pragma unroll
        for (int nt = 0; nt < 8; nt++)
            #pragma unroll
            for (int j = 0; j < 4; j++) c[mt][nt][j] = 0.f;

    #pragma unroll 1
    for (int ks = 0; ks < 16; ks++) {
        const int k0 = ks * 8;
        uint32_t ah[2][4], al[2][4];
        #pragma unroll
        for (int mt = 0; mt < 2; mt++) {
            const int r0 = wm * 32 + mt * 16;
            float v0 = As[(r0 + g)     * STRIDE + k0 + t];
            float v1 = As[(r0 + g + 8) * STRIDE + k0 + t];
            float v2 = As[(r0 + g)     * STRIDE + k0 + t + 4];
            float v3 = As[(r0 + g + 8) * STRIDE + k0 + t + 4];
            cvt_split(v0, ah[mt][0], al[mt][0]);
            cvt_split(v1, ah[mt][1], al[mt][1]);
            cvt_split(v2, ah[mt][2], al[mt][2]);
            cvt_split(v3, ah[mt][3], al[mt][3]);
        }
        #pragma unroll
        for (int nt = 0; nt < 8; nt++) {
            const int n = wn * 64 + nt * 8 + g;
            float w0 = Bs[n * STRIDE + k0 + t];
            float w1 = Bs[n * STRIDE + k0 + t + 4];
            uint32_t bh0, bl0, bh1, bl1;
            cvt_split(w0, bh0, bl0);
            cvt_split(w1, bh1, bl1);
            #pragma unroll
            for (int mt = 0; mt < 2; mt++) {
                mma8(c[mt][nt], ah[mt], bh0, bh1);
                mma8(c[mt][nt], al[mt], bh0, bh1);
                mma8(c[mt][nt], ah[mt], bl0, bl1);
            }
        }
    }

    #pragma unroll
    for (int mt = 0; mt < 2; mt++) {
        #pragma unroll
        for (int nt = 0; nt < 8; nt++) {
            const int row_a = row0 + wm * 32 + mt * 16 + g;
            const int row_b = row_a + 8;
            const int h2col = blockIdx.y * 64 + wn * 32 + nt * 4 + t;
            if (row_a < N_NODES)
                g_x2[(size_t)row_a * 128 + h2col] =
                    __floats2half2_rn(c[mt][nt][0], c[mt][nt][1]);
            if (row_b < N_NODES)
                g_x2[(size_t)row_b * 128 + h2col] =
                    __floats2half2_rn(c[mt][nt][2], c[mt][nt][3]);
        }
    }
}

// ---------------------------------------------------------------------------
// Counting sort chain (multi-block scan — the single-block version was a
// one-SM wavefront disaster; reverted to the R6 structure).
// ---------------------------------------------------------------------------
#define E4 (E_EDGES / 4)   // 200000

__global__ void hist_kernel(const int* __restrict__ r1, const int* __restrict__ r2) {
    int t = blockIdx.x * blockDim.x + threadIdx.x;
    if (t >= 2 * E4) return;
    int rel = (t >= E4);
    const int4* rr = (const int4*)(rel ? r2 : r1);
    int4 r = __ldg(rr + (t - rel * E4));
    int base = rel * N_NODES;
    atomicAdd(&g_counts[base + r.x], 1);
    atomicAdd(&g_counts[base + r.y], 1);
    atomicAdd(&g_counts[base + r.z], 1);
    atomicAdd(&g_counts[base + r.w], 1);
}

__global__ void __launch_bounds__(SCAN_B) scan1_kernel() {
    __shared__ int s[SCAN_B];
    int i = blockIdx.x * SCAN_B + threadIdx.x;
    int v = (i < M_CNT) ? g_counts[i] : 0;
    s[threadIdx.x] = v;
    __syncthreads();
    for (int off = 1; off < SCAN_B; off <<= 1) {
        int u = 0;
        if ((int)threadIdx.x >= off) u = s[threadIdx.x - off];
        __syncthreads();
        if ((int)threadIdx.x >= off) s[threadIdx.x] += u;
        __syncthreads();
    }
    if (i < M_CNT) g_tmp[i] = s[threadIdx.x] - v;
    if (threadIdx.x == SCAN_B - 1) g_bsum[blockIdx.x] = s[SCAN_B - 1];
}

// scan3: inline block-offset (first warp sums g_bsum[0..blockIdx)), writes
// g_start/g_cursor, and zeroes g_counts for the next replay (memset-free).
__global__ void __launch_bounds__(SCAN_B) scan3_kernel() {
    __shared__ int s_off;
    int t = threadIdx.x;
    if (t < 32) {
        int p = 0;
        for (int j = t; j < (int)blockIdx.x; j += 32) p += g_bsum[j];
        #pragma unroll
        for (int o = 16; o > 0; o >>= 1)
            p += __shfl_down_sync(0xffffffff, p, o);
        if (t == 0) s_off = p;
    }
    __syncthreads();
    int i = blockIdx.x * SCAN_B + t;
    if (i < M_CNT) {
        int v = g_tmp[i] + s_off;
        g_start[i]  = v;
        g_cursor[i] = v;
        g_counts[i] = 0;
    }
    if (i == 0) g_start[M_CNT] = 2 * E_EDGES;
}

__global__ void reorder_kernel(
    const int* __restrict__ r1, const int* __restrict__ c1, const float* __restrict__ v1,
    const int* __restrict__ r2, const int* __restrict__ c2, const float* __restrict__ v2)
{
    int t = blockIdx.x * blockDim.x + threadIdx.x;
    if (t >= 2 * E4) return;
    int rel = (t >= E4);
    int i4  = t - rel * E4;
    const int4*   rr = (const int4*)  (rel ? r2 : r1);
    const int4*   cc = (const int4*)  (rel ? c2 : c1);
    const float4* vv = (const float4*)(rel ? v2 : v1);
    int4   r = __ldg(rr + i4);
    int4   c = __ldg(cc + i4);
    float4 v = __ldg(vv + i4);
    int base = rel * N_NODES;
    int p0 = atomicAdd(&g_cursor[base + r.x], 1);
    int p1 = atomicAdd(&g_cursor[base + r.y], 1);
    int p2 = atomicAdd(&g_cursor[base + r.z], 1);
    int p3 = atomicAdd(&g_cursor[base + r.w], 1);
    g_edges[p0] = make_float2(__int_as_float(c.x), v.x);
    g_edges[p1] = make_float2(__int_as_float(c.y), v.y);
    g_edges[p2] = make_float2(__int_as_float(c.z), v.z);
    g_edges[p3] = make_float2(__int_as_float(c.w), v.w);
}

// ---------------------------------------------------------------------------
// Gather: PERSISTENT WARPS grid-striding over rows (balances per-row degree
// variance; no block-barrier coupling between rows). Per row: 16-lane
// half-warps, two relation streams interleaved (4 independent load chains),
// fp16 reads, fp32 accum, cross-half shfl reduce, fused ReLU, ST.128.
// ---------------------------------------------------------------------------
#define GATHER_BLOCKS 800
#define GATHER_WARPS  (GATHER_BLOCKS * 8)

__device__ __forceinline__ void acc_feat(float* a, float w, float4 q) {
    float2 f0 = __half22float2(*(__half2*)&q.x);
    float2 f1 = __half22float2(*(__half2*)&q.y);
    float2 f2 = __half22float2(*(__half2*)&q.z);
    float2 f3 = __half22float2(*(__half2*)&q.w);
    a[0] += w * f0.x;  a[1] += w * f0.y;
    a[2] += w * f1.x;  a[3] += w * f1.y;
    a[4] += w * f2.x;  a[5] += w * f2.y;
    a[6] += w * f3.x;  a[7] += w * f3.y;
}

__global__ void __launch_bounds__(256) gather_kernel(float* __restrict__ out)
{
    const int warp_gid = (blockIdx.x * blockDim.x + threadIdx.x) >> 5;
    const int lane = threadIdx.x & 31;
    const int half = lane >> 4;
    const int hl   = lane & 15;

    const float4* X4 = (const float4*)g_x2;   // [n][32] float4

    for (int w = warp_gid; w < N_NODES; w += GATHER_WARPS) {
        float a[8];
        #pragma unroll
        for (int j = 0; j < 8; j++) a[j] = 0.f;

        int p  = g_start[w] + half;                   // rel0 stream
        const int p_end = g_start[w + 1];
        int q  = g_start[N_NODES + w] + half;         // rel1 stream
        const int q_end = g_start[N_NODES + w + 1];

        while (p + 2 < p_end && q + 2 < q_end) {
            float2 e0 = __ldg(&g_edges[p]);
            float2 e1 = __ldg(&g_edges[p + 2]);
            float2 e2 = __ldg(&g_edges[q]);
            float2 e3 = __ldg(&g_edges[q + 2]);
            float4 q0 = __ldg(X4 + (size_t)__float_as_int(e0.x) * 32 + hl);
            float4 q1 = __ldg(X4 + (size_t)__float_as_int(e1.x) * 32 + hl);
            float4 q2 = __ldg(X4 + (size_t)__float_as_int(e2.x) * 32 + 16 + hl);
            float4 q3 = __ldg(X4 + (size_t)__float_as_int(e3.x) * 32 + 16 + hl);
            acc_feat(a, e0.y, q0);
            acc_feat(a, e1.y, q1);
            acc_feat(a, e2.y, q2);
            acc_feat(a, e3.y, q3);
            p += 4;
            q += 4;
        }
        for (; p < p_end; p += 2) {
            float2 e = __ldg(&g_edges[p]);
            float4 qv = __ldg(X4 + (size_t)__float_as_int(e.x) * 32 + hl);
            acc_feat(a, e.y, qv);
        }
        for (; q < q_end; q += 2) {
            float2 e = __ldg(&g_edges[q]);
            float4 qv = __ldg(X4 + (size_t)__float_as_int(e.x) * 32 + 16 + hl);
            acc_feat(a, e.y, qv);
        }

        #pragma unroll
        for (int j = 0; j < 8; j++)
            a[j] += __shfl_xor_sync(0xffffffff, a[j], 16);

        const int j0 = half * 4;
        float4 o;
        o.x = fmaxf(a[j0 + 0], 0.f);
        o.y = fmaxf(a[j0 + 1], 0.f);
        o.z = fmaxf(a[j0 + 2], 0.f);
        o.w = fmaxf(a[j0 + 3], 0.f);
        ((float4*)out)[(size_t)w * 32 + hl * 2 + half] = o;
    }
}

// ---------------------------------------------------------------------------
extern "C" void kernel_launch(void* const* d_in, const int* in_sizes, int n_in,
                              void* d_out, int out_size)
{
    const float* inputs = (const float*)d_in[0];
    const int*   r1     = (const int*)  d_in[1];
    const int*   c1     = (const int*)  d_in[2];
    const float* v1     = (const float*)d_in[3];
    const int*   r2     = (const int*)  d_in[4];
    const int*   c2     = (const int*)  d_in[5];
    const float* v2     = (const float*)d_in[6];
    const float* W1     = (const float*)d_in[7];
    const float* W2     = (const float*)d_in[8];
    float*       out    = (float*)d_out;

    static cudaStream_t s_gemm = nullptr;
    static cudaEvent_t  e_fork = nullptr;
    static cudaEvent_t  e_join = nullptr;
    if (s_gemm == nullptr) {
        cudaStreamCreateWithFlags(&s_gemm, cudaStreamNonBlocking);
        cudaEventCreateWithFlags(&e_fork, cudaEventDisableTiming);
        cudaEventCreateWithFlags(&e_join, cudaEventDisableTiming);
        cudaFuncSetAttribute(gemm_tc_kernel,
                             cudaFuncAttributeMaxDynamicSharedMemorySize,
                             GEMM_SMEM_BYTES);
    }

    // GEMM on side stream, overlapping the sort chain.
    cudaEventRecord(e_fork, 0);
    cudaStreamWaitEvent(s_gemm, e_fork, 0);
    {
        dim3 grid((N_NODES + 127) / 128, 2);
        gemm_tc_kernel<<<grid, 256, GEMM_SMEM_BYTES, s_gemm>>>(inputs, W1, W2);
    }
    cudaEventRecord(e_join, s_gemm);

    // Sort chain (counts zeroed by previous run's scan3; zero at load initially).
    hist_kernel<<<(2 * E4 + 255) / 256, 256>>>(r1, r2);
    scan1_kernel<<<NBLK_SCAN, SCAN_B>>>();
    scan3_kernel<<<NBLK_SCAN, SCAN_B>>>();
    reorder_kernel<<<(2 * E4 + 255) / 256, 256>>>(r1, c1, v1, r2, c2, v2);

    // Join, then persistent-warp gather + fused ReLU.
    cudaStreamWaitEvent(0, e_join, 0);
    gather_kernel<<<GATHER_BLOCKS, 256>>>(out);
}

// round 9
// speedup vs baseline: 2.1829x; 1.1086x over previous
#include <cuda_runtime.h>
#include <cuda_fp16.h>
#include <cstdint>

#define N_NODES 50000
#define E_EDGES 800000
#define ODIM 128
#define SCAN_B 1024
#define NBLK_SCAN ((N_NODES + SCAN_B - 1) / SCAN_B)   // 49

// Projected features fp16: [n][128] half2 (rel0 = half2 cols 0..63, rel1 = 64..127)
__device__ __half2 g_x2[(size_t)N_NODES * 128];
// Row-sorted edges: (col | rel<<16 bits, val) — buckets are row-only
__device__ float2  g_edges[(size_t)2 * E_EDGES];
__device__ int     g_rank[(size_t)2 * E_EDGES];    // per-edge rank within its row bucket
__device__ int     g_counts[N_NODES];   // zero at load; scan3 re-zeroes every run
__device__ int     g_tmp[N_NODES];
__device__ int     g_bsum[NBLK_SCAN];
__device__ int     g_start[N_NODES + 1];

// ---------------------------------------------------------------------------
// Tensor-core GEMM (tf32 x3 split) — unchanged.
// ---------------------------------------------------------------------------
#define STRIDE 132
#define GEMM_SMEM_BYTES (2 * 128 * STRIDE * 4)   // 132 KB

__device__ __forceinline__ void cvt_split(float v, uint32_t& hi, uint32_t& lo) {
    asm("cvt.rna.tf32.f32 %0, %1;" : "=r"(hi) : "f"(v));
    float r = v - __uint_as_float(hi);
    asm("cvt.rna.tf32.f32 %0, %1;" : "=r"(lo) : "f"(r));
}

__device__ __forceinline__ void mma8(float* c, const uint32_t* a,
                                     uint32_t b0, uint32_t b1) {
    asm volatile(
        "mma.sync.aligned.m16n8k8.row.col.f32.tf32.tf32.f32 "
        "{%0,%1,%2,%3}, {%4,%5,%6,%7}, {%8,%9}, {%0,%1,%2,%3};"
        : "+f"(c[0]), "+f"(c[1]), "+f"(c[2]), "+f"(c[3])
        : "r"(a[0]), "r"(a[1]), "r"(a[2]), "r"(a[3]), "r"(b0), "r"(b1));
}

__global__ void __launch_bounds__(256) gemm_tc_kernel(
    const float* __restrict__ A,
    const float* __restrict__ W1,
    const float* __restrict__ W2)
{
    extern __shared__ float smem[];
    float* As = smem;
    float* Bs = smem + 128 * STRIDE;

    const float* W = (blockIdx.y == 0) ? W1 : W2;
    const int row0 = blockIdx.x * 128;
    const int tid  = threadIdx.x;

    const float4* A4 = (const float4*)A;
    #pragma unroll
    for (int i = 0; i < 16; i++) {
        int idx = tid + i * 256;
        int m   = idx >> 5;
        int c4  = idx & 31;
        float4 v = make_float4(0.f, 0.f, 0.f, 0.f);
        if (row0 + m < N_NODES) v = A4[(size_t)(row0 + m) * 32 + c4];
        float* dst = As + m * STRIDE + c4 * 4;
        dst[0] = v.x; dst[1] = v.y; dst[2] = v.z; dst[3] = v.w;
    }
    const float4* W4 = (const float4*)W;
    #pragma unroll
    for (int i = 0; i < 16; i++) {
        int idx = tid + i * 256;
        int k   = idx >> 5;
        int n4  = idx & 31;
        float4 v = W4[idx];
        Bs[(n4 * 4 + 0) * STRIDE + k] = v.x;
        Bs[(n4 * 4 + 1) * STRIDE + k] = v.y;
        Bs[(n4 * 4 + 2) * STRIDE + k] = v.z;
        Bs[(n4 * 4 + 3) * STRIDE + k] = v.w;
    }
    __syncthreads();

    const int wid  = tid >> 5;
    const int lane = tid & 31;
    const int wm   = wid & 3;
    const int wn   = wid >> 2;
    const int g    = lane >> 2;
    const int t    = lane & 3;

    float c[2][8][4];
    #pragma unroll
    for (int mt = 0; mt < 2; mt++)
        #pragma unroll
        for (int nt = 0; nt < 8; nt++)
            #pragma unroll
            for (int j = 0; j < 4; j++) c[mt][nt][j] = 0.f;

    #pragma unroll 1
    for (int ks = 0; ks < 16; ks++) {
        const int k0 = ks * 8;
        uint32_t ah[2][4], al[2][4];
        #pragma unroll
        for (int mt = 0; mt < 2; mt++) {
            const int r0 = wm * 32 + mt * 16;
            float v0 = As[(r0 + g)     * STRIDE + k0 + t];
            float v1 = As[(r0 + g + 8) * STRIDE + k0 + t];
            float v2 = As[(r0 + g)     * STRIDE + k0 + t + 4];
            float v3 = As[(r0 + g + 8) * STRIDE + k0 + t + 4];
            cvt_split(v0, ah[mt][0], al[mt][0]);
            cvt_split(v1, ah[mt][1], al[mt][1]);
            cvt_split(v2, ah[mt][2], al[mt][2]);
            cvt_split(v3, ah[mt][3], al[mt][3]);
        }
        #pragma unroll
        for (int nt = 0; nt < 8; nt++) {
            const int n = wn * 64 + nt * 8 + g;
            float w0 = Bs[n * STRIDE + k0 + t];
            float w1 = Bs[n * STRIDE + k0 + t + 4];
            uint32_t bh0, bl0, bh1, bl1;
            cvt_split(w0, bh0, bl0);
            cvt_split(w1, bh1, bl1);
            #pragma unroll
            for (int mt = 0; mt < 2; mt++) {
                mma8(c[mt][nt], ah[mt], bh0, bh1);
                mma8(c[mt][nt], al[mt], bh0, bh1);
                mma8(c[mt][nt], ah[mt], bl0, bl1);
            }
        }
    }

    #pragma unroll
    for (int mt = 0; mt < 2; mt++) {
        #pragma unroll
        for (int nt = 0; nt < 8; nt++) {
            const int row_a = row0 + wm * 32 + mt * 16 + g;
            const int row_b = row_a + 8;
            const int h2col = blockIdx.y * 64 + wn * 32 + nt * 4 + t;
            if (row_a < N_NODES)
                g_x2[(size_t)row_a * 128 + h2col] =
                    __floats2half2_rn(c[mt][nt][0], c[mt][nt][1]);
            if (row_b < N_NODES)
                g_x2[(size_t)row_b * 128 + h2col] =
                    __floats2half2_rn(c[mt][nt][2], c[mt][nt][3]);
        }
    }
}

// ---------------------------------------------------------------------------
// Counting sort chain. Buckets = row only (50k). hist stores each edge's
// rank (the atomicAdd return value) so reorder needs NO atomics.
// ---------------------------------------------------------------------------
#define E4 (E_EDGES / 4)   // 200000

__global__ void hist_kernel(const int* __restrict__ r1, const int* __restrict__ r2) {
    int t = blockIdx.x * blockDim.x + threadIdx.x;
    if (t >= 2 * E4) return;
    int rel = (t >= E4);
    int i4  = t - rel * E4;
    const int4* rr = (const int4*)(rel ? r2 : r1);
    int4 r = __ldg(rr + i4);
    int4 k;
    k.x = atomicAdd(&g_counts[r.x], 1);
    k.y = atomicAdd(&g_counts[r.y], 1);
    k.z = atomicAdd(&g_counts[r.z], 1);
    k.w = atomicAdd(&g_counts[r.w], 1);
    ((int4*)g_rank)[rel * E4 + i4] = k;     // coalesced
}

__global__ void __launch_bounds__(SCAN_B) scan1_kernel() {
    __shared__ int s[SCAN_B];
    int i = blockIdx.x * SCAN_B + threadIdx.x;
    int v = (i < N_NODES) ? g_counts[i] : 0;
    s[threadIdx.x] = v;
    __syncthreads();
    for (int off = 1; off < SCAN_B; off <<= 1) {
        int u = 0;
        if ((int)threadIdx.x >= off) u = s[threadIdx.x - off];
        __syncthreads();
        if ((int)threadIdx.x >= off) s[threadIdx.x] += u;
        __syncthreads();
    }
    if (i < N_NODES) g_tmp[i] = s[threadIdx.x] - v;
    if (threadIdx.x == SCAN_B - 1) g_bsum[blockIdx.x] = s[SCAN_B - 1];
}

// scan3: inline block offset, write g_start, zero g_counts for next replay.
__global__ void __launch_bounds__(SCAN_B) scan3_kernel() {
    __shared__ int s_off;
    int t = threadIdx.x;
    if (t < 32) {
        int p = 0;
        for (int j = t; j < (int)blockIdx.x; j += 32) p += g_bsum[j];
        #pragma unroll
        for (int o = 16; o > 0; o >>= 1)
            p += __shfl_down_sync(0xffffffff, p, o);
        if (t == 0) s_off = p;
    }
    __syncthreads();
    int i = blockIdx.x * SCAN_B + t;
    if (i < N_NODES) {
        g_start[i]  = g_tmp[i] + s_off;
        g_counts[i] = 0;
    }
    if (i == 0) g_start[N_NODES] = 2 * E_EDGES;
}

// reorder: no atomics — pos = g_start[row] + rank. Payload packs rel in bit 16.
__global__ void reorder_kernel(
    const int* __restrict__ r1, const int* __restrict__ c1, const float* __restrict__ v1,
    const int* __restrict__ r2, const int* __restrict__ c2, const float* __restrict__ v2)
{
    int t = blockIdx.x * blockDim.x + threadIdx.x;
    if (t >= 2 * E4) return;
    int rel = (t >= E4);
    int i4  = t - rel * E4;
    const int4*   rr = (const int4*)  (rel ? r2 : r1);
    const int4*   cc = (const int4*)  (rel ? c2 : c1);
    const float4* vv = (const float4*)(rel ? v2 : v1);
    int4   r = __ldg(rr + i4);
    int4   c = __ldg(cc + i4);
    float4 v = __ldg(vv + i4);
    int4   k = ((const int4*)g_rank)[rel * E4 + i4];
    const int tag = rel << 16;
    int p0 = __ldg(&g_start[r.x]) + k.x;
    int p1 = __ldg(&g_start[r.y]) + k.y;
    int p2 = __ldg(&g_start[r.z]) + k.z;
    int p3 = __ldg(&g_start[r.w]) + k.w;
    g_edges[p0] = make_float2(__int_as_float(c.x | tag), v.x);
    g_edges[p1] = make_float2(__int_as_float(c.y | tag), v.y);
    g_edges[p2] = make_float2(__int_as_float(c.z | tag), v.z);
    g_edges[p3] = make_float2(__int_as_float(c.w | tag), v.w);
}

// ---------------------------------------------------------------------------
// Gather: one warp per row (R6 shape — proven fastest). Single merged edge
// stream per row (rel decoded from bit 16). 16-lane half-warps take
// alternating edges, 4x unrolled (8 loads in flight per warp).
// fp16 reads, fp32 accum, cross-half shfl reduce, fused ReLU, ST.128.
// ---------------------------------------------------------------------------
__device__ __forceinline__ void acc_feat(float* a, float w, float4 q) {
    float2 f0 = __half22float2(*(__half2*)&q.x);
    float2 f1 = __half22float2(*(__half2*)&q.y);
    float2 f2 = __half22float2(*(__half2*)&q.z);
    float2 f3 = __half22float2(*(__half2*)&q.w);
    a[0] += w * f0.x;  a[1] += w * f0.y;
    a[2] += w * f1.x;  a[3] += w * f1.y;
    a[4] += w * f2.x;  a[5] += w * f2.y;
    a[6] += w * f3.x;  a[7] += w * f3.y;
}

__device__ __forceinline__ const float4* feat_ptr(const float4* X4, float2 e, int hl) {
    int u   = __float_as_int(e.x);
    int col = u & 0xFFFF;
    int ro  = (u >> 16) << 4;     // rel * 16
    return X4 + (size_t)col * 32 + ro + hl;
}

__global__ void __launch_bounds__(256) gather_kernel(float* __restrict__ out)
{
    const int w    = (blockIdx.x * blockDim.x + threadIdx.x) >> 5;
    const int lane = threadIdx.x & 31;
    if (w >= N_NODES) return;

    const int half = lane >> 4;
    const int hl   = lane & 15;

    float a[8];
    #pragma unroll
    for (int j = 0; j < 8; j++) a[j] = 0.f;

    const float4* X4 = (const float4*)g_x2;   // [n][32] float4

    int p = g_start[w] + half;
    const int en = g_start[w + 1];

    // 4 edges per half-warp per iteration -> 8 independent loads in flight.
    for (; p + 6 < en; p += 8) {
        float2 e0 = __ldg(&g_edges[p]);
        float2 e1 = __ldg(&g_edges[p + 2]);
        float2 e2 = __ldg(&g_edges[p + 4]);
        float2 e3 = __ldg(&g_edges[p + 6]);
        float4 q0 = __ldg(feat_ptr(X4, e0, hl));
        float4 q1 = __ldg(feat_ptr(X4, e1, hl));
        float4 q2 = __ldg(feat_ptr(X4, e2, hl));
        float4 q3 = __ldg(feat_ptr(X4, e3, hl));
        acc_feat(a, e0.y, q0);
        acc_feat(a, e1.y, q1);
        acc_feat(a, e2.y, q2);
        acc_feat(a, e3.y, q3);
    }
    for (; p < en; p += 2) {
        float2 e = __ldg(&g_edges[p]);
        float4 q = __ldg(feat_ptr(X4, e, hl));
        acc_feat(a, e.y, q);
    }

    #pragma unroll
    for (int j = 0; j < 8; j++)
        a[j] += __shfl_xor_sync(0xffffffff, a[j], 16);

    const int j0 = half * 4;
    float4 o;
    o.x = fmaxf(a[j0 + 0], 0.f);
    o.y = fmaxf(a[j0 + 1], 0.f);
    o.z = fmaxf(a[j0 + 2], 0.f);
    o.w = fmaxf(a[j0 + 3], 0.f);
    ((float4*)out)[(size_t)w * 32 + hl * 2 + half] = o;
}

// ---------------------------------------------------------------------------
extern "C" void kernel_launch(void* const* d_in, const int* in_sizes, int n_in,
                              void* d_out, int out_size)
{
    const float* inputs = (const float*)d_in[0];
    const int*   r1     = (const int*)  d_in[1];
    const int*   c1     = (const int*)  d_in[2];
    const float* v1     = (const float*)d_in[3];
    const int*   r2     = (const int*)  d_in[4];
    const int*   c2     = (const int*)  d_in[5];
    const float* v2     = (const float*)d_in[6];
    const float* W1     = (const float*)d_in[7];
    const float* W2     = (const float*)d_in[8];
    float*       out    = (float*)d_out;

    static cudaStream_t s_gemm = nullptr;
    static cudaEvent_t  e_fork = nullptr;
    static cudaEvent_t  e_join = nullptr;
    if (s_gemm == nullptr) {
        cudaStreamCreateWithFlags(&s_gemm, cudaStreamNonBlocking);
        cudaEventCreateWithFlags(&e_fork, cudaEventDisableTiming);
        cudaEventCreateWithFlags(&e_join, cudaEventDisableTiming);
        cudaFuncSetAttribute(gemm_tc_kernel,
                             cudaFuncAttributeMaxDynamicSharedMemorySize,
                             GEMM_SMEM_BYTES);
    }

    // GEMM on side stream, overlapping the sort chain.
    cudaEventRecord(e_fork, 0);
    cudaStreamWaitEvent(s_gemm, e_fork, 0);
    {
        dim3 grid((N_NODES + 127) / 128, 2);
        gemm_tc_kernel<<<grid, 256, GEMM_SMEM_BYTES, s_gemm>>>(inputs, W1, W2);
    }
    cudaEventRecord(e_join, s_gemm);

    // Sort chain (counters zeroed by previous run's scan3; zero at load initially).
    hist_kernel<<<(2 * E4 + 255) / 256, 256>>>(r1, r2);
    scan1_kernel<<<NBLK_SCAN, SCAN_B>>>();
    scan3_kernel<<<NBLK_SCAN, SCAN_B>>>();
    reorder_kernel<<<(2 * E4 + 255) / 256, 256>>>(r1, c1, v1, r2, c2, v2);

    // Join, then warp-per-row gather + fused ReLU.
    cudaStreamWaitEvent(0, e_join, 0);
    {
        long warps = N_NODES;
        int blocks = (int)((warps * 32 + 255) / 256);
        gather_kernel<<<blocks, 256>>>(out);
    }
}

// round 11
// speedup vs baseline: 2.1878x; 1.0022x over previous
#include <cuda_runtime.h>
#include <cuda_fp16.h>
#include <cstdint>

#define N_NODES 50000
#define E_EDGES 800000
#define ODIM 128
#define SCAN_B 1024
#define NBLK_SCAN ((N_NODES + SCAN_B - 1) / SCAN_B)   // 49

// Projected features fp16: [n][128] half2 (rel0 = half2 cols 0..63, rel1 = 64..127)
__device__ __half2 g_x2[(size_t)N_NODES * 128];
// Row-sorted edges: (col | rel<<16 bits, val) — buckets are row-only
__device__ float2  g_edges[(size_t)2 * E_EDGES];
__device__ int     g_rank[(size_t)2 * E_EDGES];    // per-edge rank within its row bucket
__device__ int     g_counts[N_NODES];   // zero at load; scan3 re-zeroes every run
__device__ int     g_tmp[N_NODES];
__device__ int     g_bsum[NBLK_SCAN];
__device__ int     g_start[N_NODES + 1];

// ---------------------------------------------------------------------------
// Tensor-core GEMM (tf32 x3 split) — unchanged.
// ---------------------------------------------------------------------------
#define STRIDE 132
#define GEMM_SMEM_BYTES (2 * 128 * STRIDE * 4)   // 132 KB

__device__ __forceinline__ void cvt_split(float v, uint32_t& hi, uint32_t& lo) {
    asm("cvt.rna.tf32.f32 %0, %1;" : "=r"(hi) : "f"(v));
    float r = v - __uint_as_float(hi);
    asm("cvt.rna.tf32.f32 %0, %1;" : "=r"(lo) : "f"(r));
}

__device__ __forceinline__ void mma8(float* c, const uint32_t* a,
                                     uint32_t b0, uint32_t b1) {
    asm volatile(
        "mma.sync.aligned.m16n8k8.row.col.f32.tf32.tf32.f32 "
        "{%0,%1,%2,%3}, {%4,%5,%6,%7}, {%8,%9}, {%0,%1,%2,%3};"
        : "+f"(c[0]), "+f"(c[1]), "+f"(c[2]), "+f"(c[3])
        : "r"(a[0]), "r"(a[1]), "r"(a[2]), "r"(a[3]), "r"(b0), "r"(b1));
}

__global__ void __launch_bounds__(256) gemm_tc_kernel(
    const float* __restrict__ A,
    const float* __restrict__ W1,
    const float* __restrict__ W2)
{
    extern __shared__ float smem[];
    float* As = smem;
    float* Bs = smem + 128 * STRIDE;

    const float* W = (blockIdx.y == 0) ? W1 : W2;
    const int row0 = blockIdx.x * 128;
    const int tid  = threadIdx.x;

    const float4* A4 = (const float4*)A;
    #pragma unroll
    for (int i = 0; i < 16; i++) {
        int idx = tid + i * 256;
        int m   = idx >> 5;
        int c4  = idx & 31;
        float4 v = make_float4(0.f, 0.f, 0.f, 0.f);
        if (row0 + m < N_NODES) v = A4[(size_t)(row0 + m) * 32 + c4];
        float* dst = As + m * STRIDE + c4 * 4;
        dst[0] = v.x; dst[1] = v.y; dst[2] = v.z; dst[3] = v.w;
    }
    const float4* W4 = (const float4*)W;
    #pragma unroll
    for (int i = 0; i < 16; i++) {
        int idx = tid + i * 256;
        int k   = idx >> 5;
        int n4  = idx & 31;
        float4 v = W4[idx];
        Bs[(n4 * 4 + 0) * STRIDE + k] = v.x;
        Bs[(n4 * 4 + 1) * STRIDE + k] = v.y;
        Bs[(n4 * 4 + 2) * STRIDE + k] = v.z;
        Bs[(n4 * 4 + 3) * STRIDE + k] = v.w;
    }
    __syncthreads();

    const int wid  = tid >> 5;
    const int lane = tid & 31;
    const int wm   = wid & 3;
    const int wn   = wid >> 2;
    const int g    = lane >> 2;
    const int t    = lane & 3;

    float c[2][8][4];
    #pragma unroll
    for (int mt = 0; mt < 2; mt++)
        #pragma unroll
        for (int nt = 0; nt < 8; nt++)
            #pragma unroll
            for (int j = 0; j < 4; j++) c[mt][nt][j] = 0.f;

    #pragma unroll 1
    for (int ks = 0; ks < 16; ks++) {
        const int k0 = ks * 8;
        uint32_t ah[2][4], al[2][4];
        #pragma unroll
        for (int mt = 0; mt < 2; mt++) {
            const int r0 = wm * 32 + mt * 16;
            float v0 = As[(r0 + g)     * STRIDE + k0 + t];
            float v1 = As[(r0 + g + 8) * STRIDE + k0 + t];
            float v2 = As[(r0 + g)     * STRIDE + k0 + t + 4];
            float v3 = As[(r0 + g + 8) * STRIDE + k0 + t + 4];
            cvt_split(v0, ah[mt][0], al[mt][0]);
            cvt_split(v1, ah[mt][1], al[mt][1]);
            cvt_split(v2, ah[mt][2], al[mt][2]);
            cvt_split(v3, ah[mt][3], al[mt][3]);
        }
        #pragma unroll
        for (int nt = 0; nt < 8; nt++) {
            const int n = wn * 64 + nt * 8 + g;
            float w0 = Bs[n * STRIDE + k0 + t];
            float w1 = Bs[n * STRIDE + k0 + t + 4];
            uint32_t bh0, bl0, bh1, bl1;
            cvt_split(w0, bh0, bl0);
            cvt_split(w1, bh1, bl1);
            #pragma unroll
            for (int mt = 0; mt < 2; mt++) {
                mma8(c[mt][nt], ah[mt], bh0, bh1);
                mma8(c[mt][nt], al[mt], bh0, bh1);
                mma8(c[mt][nt], ah[mt], bl0, bl1);
            }
        }
    }

    #pragma unroll
    for (int mt = 0; mt < 2; mt++) {
        #pragma unroll
        for (int nt = 0; nt < 8; nt++) {
            const int row_a = row0 + wm * 32 + mt * 16 + g;
            const int row_b = row_a + 8;
            const int h2col = blockIdx.y * 64 + wn * 32 + nt * 4 + t;
            if (row_a < N_NODES)
                g_x2[(size_t)row_a * 128 + h2col] =
                    __floats2half2_rn(c[mt][nt][0], c[mt][nt][1]);
            if (row_b < N_NODES)
                g_x2[(size_t)row_b * 128 + h2col] =
                    __floats2half2_rn(c[mt][nt][2], c[mt][nt][3]);
        }
    }
}

// ---------------------------------------------------------------------------
// Counting sort chain. Buckets = row only (50k). hist stores each edge's
// rank (the atomicAdd return value) so reorder needs NO atomics.
// ---------------------------------------------------------------------------
#define E4 (E_EDGES / 4)   // 200000

__global__ void hist_kernel(const int* __restrict__ r1, const int* __restrict__ r2) {
    int t = blockIdx.x * blockDim.x + threadIdx.x;
    if (t >= 2 * E4) return;
    int rel = (t >= E4);
    int i4  = t - rel * E4;
    const int4* rr = (const int4*)(rel ? r2 : r1);
    int4 r = __ldg(rr + i4);
    int4 k;
    k.x = atomicAdd(&g_counts[r.x], 1);
    k.y = atomicAdd(&g_counts[r.y], 1);
    k.z = atomicAdd(&g_counts[r.z], 1);
    k.w = atomicAdd(&g_counts[r.w], 1);
    ((int4*)g_rank)[rel * E4 + i4] = k;     // coalesced
}

__global__ void __launch_bounds__(SCAN_B) scan1_kernel() {
    __shared__ int s[SCAN_B];
    int i = blockIdx.x * SCAN_B + threadIdx.x;
    int v = (i < N_NODES) ? g_counts[i] : 0;
    s[threadIdx.x] = v;
    __syncthreads();
    for (int off = 1; off < SCAN_B; off <<= 1) {
        int u = 0;
        if ((int)threadIdx.x >= off) u = s[threadIdx.x - off];
        __syncthreads();
        if ((int)threadIdx.x >= off) s[threadIdx.x] += u;
        __syncthreads();
    }
    if (i < N_NODES) g_tmp[i] = s[threadIdx.x] - v;
    if (threadIdx.x == SCAN_B - 1) g_bsum[blockIdx.x] = s[SCAN_B - 1];
}

// scan3: inline block offset, write g_start, zero g_counts for next replay.
__global__ void __launch_bounds__(SCAN_B) scan3_kernel() {
    __shared__ int s_off;
    int t = threadIdx.x;
    if (t < 32) {
        int p = 0;
        for (int j = t; j < (int)blockIdx.x; j += 32) p += g_bsum[j];
        #pragma unroll
        for (int o = 16; o > 0; o >>= 1)
            p += __shfl_down_sync(0xffffffff, p, o);
        if (t == 0) s_off = p;
    }
    __syncthreads();
    int i = blockIdx.x * SCAN_B + t;
    if (i < N_NODES) {
        g_start[i]  = g_tmp[i] + s_off;
        g_counts[i] = 0;
    }
    if (i == 0) g_start[N_NODES] = 2 * E_EDGES;
}

// reorder: no atomics — pos = g_start[row] + rank. Payload packs rel in bit 16.
__global__ void reorder_kernel(
    const int* __restrict__ r1, const int* __restrict__ c1, const float* __restrict__ v1,
    const int* __restrict__ r2, const int* __restrict__ c2, const float* __restrict__ v2)
{
    int t = blockIdx.x * blockDim.x + threadIdx.x;
    if (t >= 2 * E4) return;
    int rel = (t >= E4);
    int i4  = t - rel * E4;
    const int4*   rr = (const int4*)  (rel ? r2 : r1);
    const int4*   cc = (const int4*)  (rel ? c2 : c1);
    const float4* vv = (const float4*)(rel ? v2 : v1);
    int4   r = __ldg(rr + i4);
    int4   c = __ldg(cc + i4);
    float4 v = __ldg(vv + i4);
    int4   k = ((const int4*)g_rank)[rel * E4 + i4];
    const int tag = rel << 16;
    int p0 = __ldg(&g_start[r.x]) + k.x;
    int p1 = __ldg(&g_start[r.y]) + k.y;
    int p2 = __ldg(&g_start[r.z]) + k.z;
    int p3 = __ldg(&g_start[r.w]) + k.w;
    g_edges[p0] = make_float2(__int_as_float(c.x | tag), v.x);
    g_edges[p1] = make_float2(__int_as_float(c.y | tag), v.y);
    g_edges[p2] = make_float2(__int_as_float(c.z | tag), v.z);
    g_edges[p3] = make_float2(__int_as_float(c.w | tag), v.w);
}

// ---------------------------------------------------------------------------
// Gather: one warp per row (R6 shape — proven fastest). Single merged edge
// stream per row (rel decoded from bit 16). 16-lane half-warps take
// alternating edges, 4x unrolled (8 loads in flight per warp).
// fp16 reads, fp32 accum, cross-half shfl reduce, fused ReLU, ST.128.
// ---------------------------------------------------------------------------
__device__ __forceinline__ void acc_feat(float* a, float w, float4 q) {
    float2 f0 = __half22float2(*(__half2*)&q.x);
    float2 f1 = __half22float2(*(__half2*)&q.y);
    float2 f2 = __half22float2(*(__half2*)&q.z);
    float2 f3 = __half22float2(*(__half2*)&q.w);
    a[0] += w * f0.x;  a[1] += w * f0.y;
    a[2] += w * f1.x;  a[3] += w * f1.y;
    a[4] += w * f2.x;  a[5] += w * f2.y;
    a[6] += w * f3.x;  a[7] += w * f3.y;
}

__device__ __forceinline__ const float4* feat_ptr(const float4* X4, float2 e, int hl) {
    int u   = __float_as_int(e.x);
    int col = u & 0xFFFF;
    int ro  = (u >> 16) << 4;     // rel * 16
    return X4 + (size_t)col * 32 + ro + hl;
}

__global__ void __launch_bounds__(256) gather_kernel(float* __restrict__ out)
{
    const int w    = (blockIdx.x * blockDim.x + threadIdx.x) >> 5;
    const int lane = threadIdx.x & 31;
    if (w >= N_NODES) return;

    const int half = lane >> 4;
    const int hl   = lane & 15;

    float a[8];
    #pragma unroll
    for (int j = 0; j < 8; j++) a[j] = 0.f;

    const float4* X4 = (const float4*)g_x2;   // [n][32] float4

    int p = g_start[w] + half;
    const int en = g_start[w + 1];

    // 4 edges per half-warp per iteration -> 8 independent loads in flight.
    for (; p + 6 < en; p += 8) {
        float2 e0 = __ldg(&g_edges[p]);
        float2 e1 = __ldg(&g_edges[p + 2]);
        float2 e2 = __ldg(&g_edges[p + 4]);
        float2 e3 = __ldg(&g_edges[p + 6]);
        float4 q0 = __ldg(feat_ptr(X4, e0, hl));
        float4 q1 = __ldg(feat_ptr(X4, e1, hl));
        float4 q2 = __ldg(feat_ptr(X4, e2, hl));
        float4 q3 = __ldg(feat_ptr(X4, e3, hl));
        acc_feat(a, e0.y, q0);
        acc_feat(a, e1.y, q1);
        acc_feat(a, e2.y, q2);
        acc_feat(a, e3.y, q3);
    }
    for (; p < en; p += 2) {
        float2 e = __ldg(&g_edges[p]);
        float4 q = __ldg(feat_ptr(X4, e, hl));
        acc_feat(a, e.y, q);
    }

    #pragma unroll
    for (int j = 0; j < 8; j++)
        a[j] += __shfl_xor_sync(0xffffffff, a[j], 16);

    const int j0 = half * 4;
    float4 o;
    o.x = fmaxf(a[j0 + 0], 0.f);
    o.y = fmaxf(a[j0 + 1], 0.f);
    o.z = fmaxf(a[j0 + 2], 0.f);
    o.w = fmaxf(a[j0 + 3], 0.f);
    ((float4*)out)[(size_t)w * 32 + hl * 2 + half] = o;
}

// ---------------------------------------------------------------------------
extern "C" void kernel_launch(void* const* d_in, const int* in_sizes, int n_in,
                              void* d_out, int out_size)
{
    const float* inputs = (const float*)d_in[0];
    const int*   r1     = (const int*)  d_in[1];
    const int*   c1     = (const int*)  d_in[2];
    const float* v1     = (const float*)d_in[3];
    const int*   r2     = (const int*)  d_in[4];
    const int*   c2     = (const int*)  d_in[5];
    const float* v2     = (const float*)d_in[6];
    const float* W1     = (const float*)d_in[7];
    const float* W2     = (const float*)d_in[8];
    float*       out    = (float*)d_out;

    static cudaStream_t s_gemm = nullptr;
    static cudaEvent_t  e_fork = nullptr;
    static cudaEvent_t  e_join = nullptr;
    if (s_gemm == nullptr) {
        cudaStreamCreateWithFlags(&s_gemm, cudaStreamNonBlocking);
        cudaEventCreateWithFlags(&e_fork, cudaEventDisableTiming);
        cudaEventCreateWithFlags(&e_join, cudaEventDisableTiming);
        cudaFuncSetAttribute(gemm_tc_kernel,
                             cudaFuncAttributeMaxDynamicSharedMemorySize,
                             GEMM_SMEM_BYTES);
    }

    // GEMM on side stream, overlapping the sort chain.
    cudaEventRecord(e_fork, 0);
    cudaStreamWaitEvent(s_gemm, e_fork, 0);
    {
        dim3 grid((N_NODES + 127) / 128, 2);
        gemm_tc_kernel<<<grid, 256, GEMM_SMEM_BYTES, s_gemm>>>(inputs, W1, W2);
    }
    cudaEventRecord(e_join, s_gemm);

    // Sort chain (counters zeroed by previous run's scan3; zero at load initially).
    hist_kernel<<<(2 * E4 + 255) / 256, 256>>>(r1, r2);
    scan1_kernel<<<NBLK_SCAN, SCAN_B>>>();
    scan3_kernel<<<NBLK_SCAN, SCAN_B>>>();
    reorder_kernel<<<(2 * E4 + 255) / 256, 256>>>(r1, c1, v1, r2, c2, v2);

    // Join, then warp-per-row gather + fused ReLU.
    cudaStreamWaitEvent(0, e_join, 0);
    {
        long warps = N_NODES;
        int blocks = (int)((warps * 32 + 255) / 256);
        gather_kernel<<<blocks, 256>>>(out);
    }
}